// round 14
// baseline (speedup 1.0000x reference)
#include <cuda_runtime.h>
#include <cuda_bf16.h>
#include <cuda_fp16.h>
#include <math.h>

// Problem dims (fixed by the reference)
#define BB 64
#define TT 1024
#define II 256
#define H1 512
#define H2 512
#define OO 128
#define MM (BB * TT)   // 65536 rows
#define NBLK 16        // 64-step spike-flag blocks per sequence

// -------- device scratch (allocation-free per harness rules) --------
__device__ unsigned char g_xf8[(size_t)MM * II];       // x in e4m3 [M, K] (16 MB)
__device__ unsigned char g_w1f8[H1 * II];              // W1 in e4m3 [N, K]
__device__ float g_sbo[OO];                            // sigmoid(bo) table
__device__ int g_cnt1[MM];                             // spike counts layer 1 per (b,t)
__device__ int g_cnt2[MM];                             // spike counts layer 2 per (b,t)
__device__ int g_blk1[BB * NBLK];                      // per-(b,64-blk) layer-1 spike flag
__device__ unsigned short g_idx1[(size_t)MM * H1];     // spike indices layer 1
__device__ unsigned short g_idx2[(size_t)MM * H2];     // spike indices layer 2

__device__ __forceinline__ float sigmoidf_dev(float v) {
    return 1.f / (1.f + expf(-v));
}

// pack 4 floats -> 4 e4m3 bytes (k order: f0 at byte 0)
__device__ __forceinline__ unsigned pack_e4m3x4(float f0, float f1, float f2, float f3) {
    unsigned r;
    asm("{\n\t.reg .b16 lo, hi;\n\t"
        "cvt.rn.satfinite.e4m3x2.f32 lo, %2, %1;\n\t"
        "cvt.rn.satfinite.e4m3x2.f32 hi, %4, %3;\n\t"
        "mov.b32 %0, {lo, hi};\n\t}"
        : "=r"(r) : "f"(f0), "f"(f1), "f"(f2), "f"(f3));
    return r;
}

// -------- kernel 0a: zero counters/flags --------
__global__ void prep_zero() {
    int idx = blockIdx.x * blockDim.x + threadIdx.x;
    if (idx < MM) { g_cnt1[idx] = 0; g_cnt2[idx] = 0; }
    if (idx < BB * NBLK) g_blk1[idx] = 0;
}

// -------- kernel 0b: W1 -> e4m3, sigmoid(bo) --------
__global__ void prep_w1(const float* __restrict__ W1,
                        const float* __restrict__ bo) {
    int idx = blockIdx.x * blockDim.x + threadIdx.x;
    if (idx < H1 * II / 4) {
        float4 v = ((const float4*)W1)[idx];
        ((unsigned*)g_w1f8)[idx] = pack_e4m3x4(v.x, v.y, v.z, v.w);
    }
    if (idx < OO) g_sbo[idx] = sigmoidf_dev(bo[idx]);
}

// -------- kernel 0c: x -> e4m3 (vectorized: 16 floats -> 16 bytes/thread) --
__global__ void prep_x(const float* __restrict__ x) {
    size_t i = (size_t)blockIdx.x * blockDim.x + threadIdx.x;   // uint4 index
    if (i < (size_t)MM * II / 16) {
        const float4* src = (const float4*)x + 4 * i;
        float4 a = src[0], b = src[1], c = src[2], d = src[3];
        uint4 v;
        v.x = pack_e4m3x4(a.x, a.y, a.z, a.w);
        v.y = pack_e4m3x4(b.x, b.y, b.z, b.w);
        v.z = pack_e4m3x4(c.x, c.y, c.z, c.w);
        v.w = pack_e4m3x4(d.x, d.y, d.z, d.w);
        ((uint4*)g_xf8)[i] = v;
    }
}

// -------- kernel 1: FUSED fp8 QMMA GEMM + layer-1 LIF scan --------
// CTA = (h-block 128, batch b). 512 threads = 16 warps in 4(t) x 4(h),
// warp tile 32x32, f16 accumulators. FULL-K staging: W1 block staged ONCE
// per CTA, x tile staged once per tile -> the 8-chunk mma loop is
// sync-free (2 barriers per tile instead of 10). Separate epilogue region
// lets the serial scan overlap next-tile x staging.
#define ROWW 76                       // stage row stride in words (304B; 12 mod 32)
#define A_OFFW 0                      // x tile region (words)
#define B_OFFW (128 * ROWW)           // W1 region (words)       = 9728
#define EPI_OFFW (2 * 128 * ROWW)     // epilogue region (words) = 19456
#define EPI_W 65                      // epilogue row stride in words (130 bf16)
#define SMEM_WORDS (EPI_OFFW + 128 * EPI_W)   // 27776 words = 111104 B
#define SMEM_BYTES (SMEM_WORDS * 4)

__global__ __launch_bounds__(512, 2)
void fused_gemm_scan1(const float* __restrict__ bias,
                      const float* __restrict__ tau_m1,
                      const float* __restrict__ tau_n1) {
    extern __shared__ __align__(16) unsigned smem[];

    const int tid  = threadIdx.x;      // 512 threads
    const int warp = tid >> 5;         // 0..15
    const int lane = tid & 31;
    const int g  = lane >> 2;          // 0..7
    const int tg = lane & 3;           // 0..3
    const int wm = (warp & 3) * 32;    // t-quadrant: 0,32,64,96
    const int wn = (warp >> 2) * 32;   // h-quadrant: 0,32,64,96

    const int n0 = blockIdx.x * 128;   // h-block base
    const int b  = blockIdx.y;         // batch

    const unsigned sbase = (unsigned)__cvta_generic_to_shared(smem);
    const int lrow8 = (lane & 7) + ((lane >> 3) & 1) * 8; // ldmatrix row-in-16
    const int lkw   = ((lane >> 4) & 1) * 4;              // k-half word offset

    // ---- prologue: stage W1 block (once) + x tile 0, all 512 threads ----
    {
        const int row = tid >> 2;       // 0..127
        const int q   = tid & 3;        // 64B quarter
        const uint4* wsrc = (const uint4*)(g_w1f8 + (size_t)(n0 + row) * II + q * 64);
        const uint4* xsrc = (const uint4*)(g_xf8 + ((size_t)b * TT + row) * II + q * 64);
        unsigned* wdst = smem + B_OFFW + row * ROWW + q * 16;
        unsigned* xdst = smem + A_OFFW + row * ROWW + q * 16;
#pragma unroll
        for (int j = 0; j < 4; j++) {
            *(uint4*)(wdst + j * 4) = wsrc[j];
            *(uint4*)(xdst + j * 4) = xsrc[j];
        }
    }

    // scan state (threads 0..127: thread = local h)
    float alpha = 0.f, beta = 0.f, oma = 0.f, omb = 0.f;
    float d_s = 0.f, m_s = 0.f;
    int hglob = 0;
    if (tid < 128) {
        hglob = n0 + tid;
        alpha = sigmoidf_dev(tau_m1[hglob]);
        beta  = sigmoidf_dev(tau_n1[hglob]);
        oma = 1.f - alpha; omb = 1.f - beta;
    }
    __syncthreads();   // W1 + x tile 0 staged

#pragma unroll 1
    for (int mt = 0; mt < 8; mt++) {
        unsigned acc[2][4][2];             // f16x2 accumulators
#pragma unroll
        for (int mi = 0; mi < 2; mi++)
#pragma unroll
            for (int nj = 0; nj < 4; nj++) {
                acc[mi][nj][0] = 0u; acc[mi][nj][1] = 0u;
            }

        // ---- k-loop: 8 chunks, fully in smem, NO syncs ----
#pragma unroll
        for (int kc = 0; kc < II / 32; kc++) {
            const int kw = kc * 8 + lkw;

            unsigned a[2][4];
#pragma unroll
            for (int mi = 0; mi < 2; mi++) {
                unsigned addr = sbase + ((A_OFFW + (wm + mi * 16 + lrow8) * ROWW + kw) << 2);
                asm volatile(
                    "ldmatrix.sync.aligned.m8n8.x4.shared.b16 {%0,%1,%2,%3}, [%4];\n"
                    : "=r"(a[mi][0]), "=r"(a[mi][1]), "=r"(a[mi][2]), "=r"(a[mi][3])
                    : "r"(addr));
            }
            unsigned bb[4][2];
#pragma unroll
            for (int jj = 0; jj < 2; jj++) {
                unsigned addr = sbase + ((B_OFFW + (wn + jj * 16 + lrow8) * ROWW + kw) << 2);
                unsigned r0, r1, r2, r3;
                asm volatile(
                    "ldmatrix.sync.aligned.m8n8.x4.shared.b16 {%0,%1,%2,%3}, [%4];\n"
                    : "=r"(r0), "=r"(r1), "=r"(r2), "=r"(r3)
                    : "r"(addr));
                bb[2 * jj][0]     = r0;
                bb[2 * jj + 1][0] = r1;
                bb[2 * jj][1]     = r2;
                bb[2 * jj + 1][1] = r3;
            }

#pragma unroll
            for (int nj = 0; nj < 4; nj++) {
#pragma unroll
                for (int mi = 0; mi < 2; mi++) {
                    asm volatile(
                        "mma.sync.aligned.m16n8k32.row.col.f16.e4m3.e4m3.f16 "
                        "{%0,%1}, {%2,%3,%4,%5}, {%6,%7}, {%0,%1};\n"
                        : "+r"(acc[mi][nj][0]), "+r"(acc[mi][nj][1])
                        : "r"(a[mi][0]), "r"(a[mi][1]), "r"(a[mi][2]), "r"(a[mi][3]),
                          "r"(bb[nj][0]), "r"(bb[nj][1]));
                }
            }
        }

        // ---- epilogue: +bias, bf16, transpose into SEPARATE epi region ----
        __nv_bfloat16* stp = (__nv_bfloat16*)(smem + EPI_OFFW);
#pragma unroll
        for (int nj = 0; nj < 4; nj++) {
            const int c0 = wn + nj * 8 + 2 * tg;    // local h
            const float bx = __ldg(&bias[n0 + c0]);
            const float by = __ldg(&bias[n0 + c0 + 1]);
#pragma unroll
            for (int mi = 0; mi < 2; mi++) {
                const int r0 = wm + mi * 16 + g;    // local t
                float2 v0 = __half22float2(*(__half2*)&acc[mi][nj][0]);  // row r0
                float2 v1 = __half22float2(*(__half2*)&acc[mi][nj][1]);  // row r0+8
                stp[c0 * (2 * EPI_W) + r0]           = __float2bfloat16_rn(v0.x + bx);
                stp[(c0 + 1) * (2 * EPI_W) + r0]     = __float2bfloat16_rn(v0.y + by);
                stp[c0 * (2 * EPI_W) + r0 + 8]       = __float2bfloat16_rn(v1.x + bx);
                stp[(c0 + 1) * (2 * EPI_W) + r0 + 8] = __float2bfloat16_rn(v1.y + by);
            }
        }
        __syncthreads();   // mma reads of A done + epi visible

        // ---- overlap: scan (thr 0..127) || stage next x tile (thr 256..511) ----
        if (tid >= 256 && mt + 1 < 8) {
            const int s    = tid - 256;      // 0..255
            const int row  = s >> 1;
            const int half = s & 1;          // 128B half
            const uint4* xsrc = (const uint4*)(g_xf8
                + ((size_t)b * TT + (mt + 1) * 128 + row) * II + half * 128);
            unsigned* xdst = smem + A_OFFW + row * ROWW + half * 32;
#pragma unroll
            for (int j = 0; j < 8; j++)
                *(uint4*)(xdst + j * 4) = xsrc[j];
        }

        if (tid < 128) {
            const unsigned* rw = smem + EPI_OFFW + tid * EPI_W;  // stride 65: conflict-free
            const int tb = b * TT + mt * 128;
#pragma unroll 8
            for (int w = 0; w < 64; w++) {
                float2 p = __bfloat1622float2(*(const __nv_bfloat162*)&rw[w]);
#pragma unroll
                for (int s = 0; s < 2; s++) {
                    const float v = (s == 0) ? p.x : p.y;
                    d_s = beta * d_s + omb * v;
                    m_s = alpha * m_s + oma * d_s;
                    const bool spk = (m_s > 1.f);
                    if (spk) {                         // ~never taken
                        const int mm = tb + 2 * w + s;
                        const int pp = atomicAdd(&g_cnt1[mm], 1);
                        g_idx1[(size_t)mm * H1 + pp] = (unsigned short)hglob;
                        atomicOr(&g_blk1[(b << 4) + ((mt * 128 + 2 * w + s) >> 6)], 1);
                    }
                    m_s = spk ? 0.f : m_s;
                }
            }
        }
        __syncthreads();   // scan reads done + next x tile staged
    }
}

// -------- kernel 3: layer-2 scan with closed-form chunk skipping --------
__global__ __launch_bounds__(128)
void scan2_kernel(const float* __restrict__ b2,
                  const float* __restrict__ tau_m2,
                  const float* __restrict__ tau_n2,
                  const float* __restrict__ W2) {
    const int idx = blockIdx.x * blockDim.x + threadIdx.x;   // 0..32767
    const int b = idx >> 9;
    const int h = idx & (H2 - 1);

    const float alpha = sigmoidf_dev(tau_m2[h]);
    const float beta  = sigmoidf_dev(tau_n2[h]);
    const float oma = 1.f - alpha, omb = 1.f - beta;
    const float b2v = b2[h];

    // one-time per-thread series constants (64 iterations)
    float a64 = 1.f, b64 = 1.f, S64 = 0.f, Cmax = 0.f, gt = 1.f;
    const float gmm = fmaxf(alpha, beta);
#pragma unroll 1
    for (int t = 1; t <= 64; t++) {
        a64 *= alpha;
        b64 *= beta;
        S64 = alpha * S64 + b64;     // b64 == beta^t here
        gt  *= gmm;
        Cmax = fmaxf(Cmax, (float)t * gt);
    }

    const int mb = b * TT;
    float d = 0.f, m = 0.f;

    int flags[16];
#pragma unroll
    for (int i = 0; i < 4; i++) {
        uint4 f = ((const uint4*)(g_blk1 + (b << 4)))[i];
        flags[4 * i + 0] = (int)f.x; flags[4 * i + 1] = (int)f.y;
        flags[4 * i + 2] = (int)f.z; flags[4 * i + 3] = (int)f.w;
    }

    auto step = [&](float din, int t) {
        d = beta * d + omb * din;
        m = alpha * m + oma * d;
        bool spk = (m > 1.f);
        if (spk) {
            int mm = mb + t;
            int pp = atomicAdd(&g_cnt2[mm], 1);
            g_idx2[(size_t)mm * H2 + pp] = (unsigned short)h;
        }
        m = spk ? 0.f : m;
    };

#pragma unroll 1
    for (int c = 0; c < 16; c++) {
        const int t0 = c * 64;
        if (flags[c] == 0) {
            const float e0  = d - b2v;
            const float mu0 = m - b2v;
            const float bnd = b2v + fabsf(mu0) + oma * fabsf(e0) * Cmax;
            if (bnd < 0.999f) {
                m = b2v + a64 * mu0 + oma * e0 * S64;
                d = b2v + b64 * e0;
            } else {
#pragma unroll 1
                for (int i = 0; i < 64; i++)
                    step(b2v, t0 + i);
            }
        } else {
#pragma unroll 1
            for (int i = 0; i < 64; i++) {
                float din = b2v;
                const int cc = __ldg(&g_cnt1[mb + t0 + i]);
                if (cc) {
                    const unsigned short* L = &g_idx1[(size_t)(mb + t0 + i) * H1];
                    for (int j = 0; j < cc; j++)
                        din += W2[(size_t)h * H1 + (int)L[j]];
                }
                step(din, t0 + i);
            }
        }
    }
}

// -------- kernel 4: output projection (precomputed-sigmoid fast path) ------
__global__ __launch_bounds__(256)
void out_proj(const float* __restrict__ bo, const float* __restrict__ Wo,
              float* __restrict__ out) {
    const int m = blockIdx.x * 8 + (threadIdx.x >> 5);
    const int o = (threadIdx.x & 31) * 4;
    const int c = g_cnt2[m];
    float4 v;
    if (c == 0) {
        v = *(const float4*)&g_sbo[o];
    } else {
        float a0 = bo[o], a1 = bo[o + 1], a2 = bo[o + 2], a3 = bo[o + 3];
        const unsigned short* L = &g_idx2[(size_t)m * H2];
        for (int j = 0; j < c; j++) {
            const int k = (int)L[j];
            a0 += Wo[(size_t)(o + 0) * H2 + k];
            a1 += Wo[(size_t)(o + 1) * H2 + k];
            a2 += Wo[(size_t)(o + 2) * H2 + k];
            a3 += Wo[(size_t)(o + 3) * H2 + k];
        }
        v.x = sigmoidf_dev(a0); v.y = sigmoidf_dev(a1);
        v.z = sigmoidf_dev(a2); v.w = sigmoidf_dev(a3);
    }
    *(float4*)&out[(size_t)m * OO + o] = v;
}

extern "C" void kernel_launch(void* const* d_in, const int* in_sizes, int n_in,
                              void* d_out, int out_size) {
    const float* x      = (const float*)d_in[0];
    const float* W1     = (const float*)d_in[1];
    const float* b1     = (const float*)d_in[2];
    const float* tau_m1 = (const float*)d_in[3];
    const float* tau_n1 = (const float*)d_in[4];
    const float* W2     = (const float*)d_in[5];
    const float* b2     = (const float*)d_in[6];
    const float* tau_m2 = (const float*)d_in[7];
    const float* tau_n2 = (const float*)d_in[8];
    const float* Wo     = (const float*)d_in[9];
    const float* bo     = (const float*)d_in[10];
    float* out = (float*)d_out;

    // allow >48KB dynamic smem (host attribute, not an allocation)
    static int smem_set = 0;
    if (!smem_set) {
        cudaFuncSetAttribute(fused_gemm_scan1,
                             cudaFuncAttributeMaxDynamicSharedMemorySize,
                             SMEM_BYTES);
        smem_set = 1;
    }

    // 0) prep (3 launches; keeps fused at launch #4 for ncu)
    prep_zero<<<(MM + 255) / 256, 256>>>();
    prep_w1<<<(H1 * II / 4 + 255) / 256, 256>>>(W1, bo);
    prep_x<<<(MM * II / 16 + 255) / 256, 256>>>(x);

    // 1+2) fused layer-1 projection (fp8 QMMA, full-K staging) + scan
    dim3 grid(H1 / 128, BB);   // (4 h-tiles, 64 batches) = 256 CTAs
    fused_gemm_scan1<<<grid, 512, SMEM_BYTES>>>(b1, tau_m1, tau_n1);

    // 3) layer-2 LIF scan (closed-form chunk jumps, certified spike-free)
    scan2_kernel<<<(BB * H2) / 128, 128>>>(b2, tau_m2, tau_n2, W2);

    // 4) output projection
    out_proj<<<MM / 8, 256>>>(bo, Wo, out);
}

// round 15
// speedup vs baseline: 1.2552x; 1.2552x over previous
#include <cuda_runtime.h>
#include <cuda_bf16.h>
#include <cuda_fp16.h>
#include <math.h>

// Problem dims (fixed by the reference)
#define BB 64
#define TT 1024
#define II 256
#define H1 512
#define H2 512
#define OO 128
#define MM (BB * TT)   // 65536 rows
#define NBLK 16        // 64-step spike-flag blocks per sequence

// -------- device scratch (allocation-free per harness rules) --------
__device__ unsigned char g_xf8[(size_t)MM * II];       // x in e4m3 [M, K] (16 MB)
__device__ unsigned char g_w1f8[H1 * II];              // W1 in e4m3 [N, K]
__device__ float g_sbo[OO];                            // sigmoid(bo) table
__device__ int g_cnt1[MM];                             // spike counts layer 1 per (b,t)
__device__ int g_cnt2[MM];                             // spike counts layer 2 per (b,t)
__device__ int g_blk1[BB * NBLK];                      // per-(b,64-blk) layer-1 spike flag
__device__ unsigned short g_idx1[(size_t)MM * H1];     // spike indices layer 1
__device__ unsigned short g_idx2[(size_t)MM * H2];     // spike indices layer 2

__device__ __forceinline__ float sigmoidf_dev(float v) {
    return 1.f / (1.f + expf(-v));
}

// pack 4 floats -> 4 e4m3 bytes (k order: f0 at byte 0)
__device__ __forceinline__ unsigned pack_e4m3x4(float f0, float f1, float f2, float f3) {
    unsigned r;
    asm("{\n\t.reg .b16 lo, hi;\n\t"
        "cvt.rn.satfinite.e4m3x2.f32 lo, %2, %1;\n\t"
        "cvt.rn.satfinite.e4m3x2.f32 hi, %4, %3;\n\t"
        "mov.b32 %0, {lo, hi};\n\t}"
        : "=r"(r) : "f"(f0), "f"(f1), "f"(f2), "f"(f3));
    return r;
}

#define BAR_SYNC(id, cnt)   asm volatile("bar.sync %0, %1;"   :: "r"(id), "r"(cnt) : "memory")
#define BAR_ARRIVE(id, cnt) asm volatile("bar.arrive %0, %1;" :: "r"(id), "r"(cnt) : "memory")

// -------- kernel 0a: zero counters/flags --------
__global__ void prep_zero() {
    int idx = blockIdx.x * blockDim.x + threadIdx.x;
    if (idx < MM) { g_cnt1[idx] = 0; g_cnt2[idx] = 0; }
    if (idx < BB * NBLK) g_blk1[idx] = 0;
}

// -------- kernel 0b: W1 -> e4m3, sigmoid(bo) --------
__global__ void prep_w1(const float* __restrict__ W1,
                        const float* __restrict__ bo) {
    int idx = blockIdx.x * blockDim.x + threadIdx.x;
    if (idx < H1 * II / 4) {
        float4 v = ((const float4*)W1)[idx];
        ((unsigned*)g_w1f8)[idx] = pack_e4m3x4(v.x, v.y, v.z, v.w);
    }
    if (idx < OO) g_sbo[idx] = sigmoidf_dev(bo[idx]);
}

// -------- kernel 0c: x -> e4m3 (vectorized: 16 floats -> 16 bytes/thread) --
__global__ void prep_x(const float* __restrict__ x) {
    size_t i = (size_t)blockIdx.x * blockDim.x + threadIdx.x;   // uint4 index
    if (i < (size_t)MM * II / 16) {
        const float4* src = (const float4*)x + 4 * i;
        float4 a = src[0], b = src[1], c = src[2], d = src[3];
        uint4 v;
        v.x = pack_e4m3x4(a.x, a.y, a.z, a.w);
        v.y = pack_e4m3x4(b.x, b.y, b.z, b.w);
        v.z = pack_e4m3x4(c.x, c.y, c.z, c.w);
        v.w = pack_e4m3x4(d.x, d.y, d.z, d.w);
        ((uint4*)g_xf8)[i] = v;
    }
}

// -------- kernel 1: WARP-SPECIALIZED fused fp8 GEMM + layer-1 LIF scan -----
// 384 threads: warps 0-7 = GEMM producer (128t x 128h tile, warp 32x64,
// f16 acc, double-buffered k=32 chunks, 1 named-bar sync per chunk);
// warps 8-11 = scan consumer (thread = h row). Two ping-pong epilogue
// buffers; full[p]/empty[p] named-barrier handoff. Tile mt+1's GEMM runs
// concurrently with tile mt's serial scan.
#define ROWW 12                     // stage row stride in words (48B)
#define STAGE_W (128 * ROWW)        // words per matrix per stage (1536)
#define EPI0 (4 * STAGE_W)          // epi region base (words) = 6144
#define EPI_W 65                    // epilogue row stride in words (130 bf16)
#define EPI_SZ (128 * EPI_W)        // words per epi buffer (8320)
#define SMEM_WORDS (EPI0 + 2 * EPI_SZ)   // 22784 words = 91136 B
#define SMEM_BYTES (SMEM_WORDS * 4)

__global__ __launch_bounds__(384, 2)
void fused_gemm_scan1(const float* __restrict__ bias,
                      const float* __restrict__ tau_m1,
                      const float* __restrict__ tau_n1) {
    extern __shared__ __align__(16) unsigned smem[];

    const int tid = threadIdx.x;       // 384 threads
    const int n0 = blockIdx.x * 128;   // h-block base
    const int b  = blockIdx.y;         // batch
    const unsigned sbase = (unsigned)__cvta_generic_to_shared(smem);

    if (tid < 256) {
        // ================= GEMM producer (8 warps) =================
        const int warp = tid >> 5;
        const int lane = tid & 31;
        const int g  = lane >> 2;          // 0..7
        const int tg = lane & 3;           // 0..3
        const int wm = (warp >> 1) * 32;   // t-quadrant
        const int wn = (warp & 1) * 64;    // h-half

        const int lrow  = tid >> 1;        // row this thread stages
        const int khalf = tid & 1;         // 16B half of 32B chunk row

        const unsigned char* xbase = g_xf8 + ((size_t)b * TT + lrow) * II + khalf * 16;
        const unsigned char* wrow  = g_w1f8 + (size_t)(n0 + lrow) * II + khalf * 16;

        const int lrow8 = (lane & 7) + ((lane >> 3) & 1) * 8;
        const int lkw   = ((lane >> 4) & 1) * 4;

        uint4 pav = *(const uint4*)(xbase);
        uint4 pbv = *(const uint4*)(wrow);

#pragma unroll 1
        for (int mt = 0; mt < 8; mt++) {
            const unsigned char* xrow = xbase + (size_t)mt * 128 * II;

            unsigned acc[2][8][2];         // f16x2 accumulators
#pragma unroll
            for (int mi = 0; mi < 2; mi++)
#pragma unroll
                for (int nj = 0; nj < 8; nj++) {
                    acc[mi][nj][0] = 0u; acc[mi][nj][1] = 0u;
                }

            // ---- k-loop: 8 chunks of k=32, double-buffered stages ----
#pragma unroll 1
            for (int kc = 0; kc < II / 32; kc++) {
                const int st = kc & 1;
                unsigned* As = smem + st * 2 * STAGE_W;
                unsigned* Bs = As + STAGE_W;

                *(uint4*)(As + lrow * ROWW + khalf * 4) = pav;
                *(uint4*)(Bs + lrow * ROWW + khalf * 4) = pbv;

                if (kc + 1 < II / 32) {
                    pav = *(const uint4*)(xrow + (kc + 1) * 32);
                    pbv = *(const uint4*)(wrow + (kc + 1) * 32);
                }

                BAR_SYNC(2, 256);          // producer-group staging sync

                const unsigned abase = sbase + (st * 2 * STAGE_W) * 4;

                unsigned a[2][4];
#pragma unroll
                for (int mi = 0; mi < 2; mi++) {
                    unsigned addr = abase + ((wm + mi * 16 + lrow8) * ROWW + lkw) * 4;
                    asm volatile(
                        "ldmatrix.sync.aligned.m8n8.x4.shared.b16 {%0,%1,%2,%3}, [%4];\n"
                        : "=r"(a[mi][0]), "=r"(a[mi][1]), "=r"(a[mi][2]), "=r"(a[mi][3])
                        : "r"(addr));
                }
                unsigned barr[8][2];
#pragma unroll
                for (int jj = 0; jj < 4; jj++) {
                    unsigned addr = abase + (STAGE_W + (wn + jj * 16 + lrow8) * ROWW + lkw) * 4;
                    unsigned r0, r1, r2, r3;
                    asm volatile(
                        "ldmatrix.sync.aligned.m8n8.x4.shared.b16 {%0,%1,%2,%3}, [%4];\n"
                        : "=r"(r0), "=r"(r1), "=r"(r2), "=r"(r3)
                        : "r"(addr));
                    barr[2 * jj][0]     = r0;
                    barr[2 * jj + 1][0] = r1;
                    barr[2 * jj][1]     = r2;
                    barr[2 * jj + 1][1] = r3;
                }

#pragma unroll
                for (int nj = 0; nj < 8; nj++) {
#pragma unroll
                    for (int mi = 0; mi < 2; mi++) {
                        asm volatile(
                            "mma.sync.aligned.m16n8k32.row.col.f16.e4m3.e4m3.f16 "
                            "{%0,%1}, {%2,%3,%4,%5}, {%6,%7}, {%0,%1};\n"
                            : "+r"(acc[mi][nj][0]), "+r"(acc[mi][nj][1])
                            : "r"(a[mi][0]), "r"(a[mi][1]), "r"(a[mi][2]), "r"(a[mi][3]),
                              "r"(barr[nj][0]), "r"(barr[nj][1]));
                    }
                }
            }

            // ---- epilogue into ping-pong buffer p ----
            const int p = mt & 1;
            if (mt >= 2) BAR_SYNC(4 + p, 384);     // wait buffer free

            __nv_bfloat16* stp = (__nv_bfloat16*)(smem + EPI0 + p * EPI_SZ);
#pragma unroll
            for (int nj = 0; nj < 8; nj++) {
                const int c0 = wn + nj * 8 + 2 * tg;    // local h
                const float bx = __ldg(&bias[n0 + c0]);
                const float by = __ldg(&bias[n0 + c0 + 1]);
#pragma unroll
                for (int mi = 0; mi < 2; mi++) {
                    const int r0 = wm + mi * 16 + g;    // local t
                    float2 v0 = __half22float2(*(__half2*)&acc[mi][nj][0]);
                    float2 v1 = __half22float2(*(__half2*)&acc[mi][nj][1]);
                    stp[c0 * (2 * EPI_W) + r0]           = __float2bfloat16_rn(v0.x + bx);
                    stp[(c0 + 1) * (2 * EPI_W) + r0]     = __float2bfloat16_rn(v0.y + by);
                    stp[c0 * (2 * EPI_W) + r0 + 8]       = __float2bfloat16_rn(v1.x + bx);
                    stp[(c0 + 1) * (2 * EPI_W) + r0 + 8] = __float2bfloat16_rn(v1.y + by);
                }
            }
            BAR_ARRIVE(p, 384);                    // publish tile mt
        }
    } else {
        // ================= scan consumer (4 warps) =================
        const int h = tid - 256;           // local h row, 0..127
        const int hglob = n0 + h;
        const float alpha = sigmoidf_dev(tau_m1[hglob]);
        const float beta  = sigmoidf_dev(tau_n1[hglob]);
        const float oma = 1.f - alpha, omb = 1.f - beta;
        float d_s = 0.f, m_s = 0.f;

#pragma unroll 1
        for (int mt = 0; mt < 8; mt++) {
            const int p = mt & 1;
            BAR_SYNC(p, 384);              // wait tile mt published

            const unsigned* rw = smem + EPI0 + p * EPI_SZ + h * EPI_W;
            const int tb = b * TT + mt * 128;
#pragma unroll 8
            for (int w = 0; w < 64; w++) {
                float2 pr = __bfloat1622float2(*(const __nv_bfloat162*)&rw[w]);
#pragma unroll
                for (int s = 0; s < 2; s++) {
                    const float v = (s == 0) ? pr.x : pr.y;
                    d_s = beta * d_s + omb * v;
                    m_s = alpha * m_s + oma * d_s;
                    const bool spk = (m_s > 1.f);
                    if (spk) {                         // ~never taken
                        const int mm = tb + 2 * w + s;
                        const int pp = atomicAdd(&g_cnt1[mm], 1);
                        g_idx1[(size_t)mm * H1 + pp] = (unsigned short)hglob;
                        atomicOr(&g_blk1[(b << 4) + ((mt * 128 + 2 * w + s) >> 6)], 1);
                    }
                    m_s = spk ? 0.f : m_s;
                }
            }
            if (mt < 6) BAR_ARRIVE(4 + p, 384);   // release buffer
        }
    }
}

// -------- kernel 3: layer-2 scan with closed-form chunk skipping --------
__global__ __launch_bounds__(128)
void scan2_kernel(const float* __restrict__ b2,
                  const float* __restrict__ tau_m2,
                  const float* __restrict__ tau_n2,
                  const float* __restrict__ W2) {
    const int idx = blockIdx.x * blockDim.x + threadIdx.x;   // 0..32767
    const int b = idx >> 9;
    const int h = idx & (H2 - 1);

    const float alpha = sigmoidf_dev(tau_m2[h]);
    const float beta  = sigmoidf_dev(tau_n2[h]);
    const float oma = 1.f - alpha, omb = 1.f - beta;
    const float b2v = b2[h];

    float a64 = 1.f, b64 = 1.f, S64 = 0.f, Cmax = 0.f, gt = 1.f;
    const float gmm = fmaxf(alpha, beta);
#pragma unroll 1
    for (int t = 1; t <= 64; t++) {
        a64 *= alpha;
        b64 *= beta;
        S64 = alpha * S64 + b64;
        gt  *= gmm;
        Cmax = fmaxf(Cmax, (float)t * gt);
    }

    const int mb = b * TT;
    float d = 0.f, m = 0.f;

    int flags[16];
#pragma unroll
    for (int i = 0; i < 4; i++) {
        uint4 f = ((const uint4*)(g_blk1 + (b << 4)))[i];
        flags[4 * i + 0] = (int)f.x; flags[4 * i + 1] = (int)f.y;
        flags[4 * i + 2] = (int)f.z; flags[4 * i + 3] = (int)f.w;
    }

    auto step = [&](float din, int t) {
        d = beta * d + omb * din;
        m = alpha * m + oma * d;
        bool spk = (m > 1.f);
        if (spk) {
            int mm = mb + t;
            int pp = atomicAdd(&g_cnt2[mm], 1);
            g_idx2[(size_t)mm * H2 + pp] = (unsigned short)h;
        }
        m = spk ? 0.f : m;
    };

#pragma unroll 1
    for (int c = 0; c < 16; c++) {
        const int t0 = c * 64;
        if (flags[c] == 0) {
            const float e0  = d - b2v;
            const float mu0 = m - b2v;
            const float bnd = b2v + fabsf(mu0) + oma * fabsf(e0) * Cmax;
            if (bnd < 0.999f) {
                m = b2v + a64 * mu0 + oma * e0 * S64;
                d = b2v + b64 * e0;
            } else {
#pragma unroll 1
                for (int i = 0; i < 64; i++)
                    step(b2v, t0 + i);
            }
        } else {
#pragma unroll 1
            for (int i = 0; i < 64; i++) {
                float din = b2v;
                const int cc = __ldg(&g_cnt1[mb + t0 + i]);
                if (cc) {
                    const unsigned short* L = &g_idx1[(size_t)(mb + t0 + i) * H1];
                    for (int j = 0; j < cc; j++)
                        din += W2[(size_t)h * H1 + (int)L[j]];
                }
                step(din, t0 + i);
            }
        }
    }
}

// -------- kernel 4: output projection (precomputed-sigmoid fast path) ------
__global__ __launch_bounds__(256)
void out_proj(const float* __restrict__ bo, const float* __restrict__ Wo,
              float* __restrict__ out) {
    const int m = blockIdx.x * 8 + (threadIdx.x >> 5);
    const int o = (threadIdx.x & 31) * 4;
    const int c = g_cnt2[m];
    float4 v;
    if (c == 0) {
        v = *(const float4*)&g_sbo[o];
    } else {
        float a0 = bo[o], a1 = bo[o + 1], a2 = bo[o + 2], a3 = bo[o + 3];
        const unsigned short* L = &g_idx2[(size_t)m * H2];
        for (int j = 0; j < c; j++) {
            const int k = (int)L[j];
            a0 += Wo[(size_t)(o + 0) * H2 + k];
            a1 += Wo[(size_t)(o + 1) * H2 + k];
            a2 += Wo[(size_t)(o + 2) * H2 + k];
            a3 += Wo[(size_t)(o + 3) * H2 + k];
        }
        v.x = sigmoidf_dev(a0); v.y = sigmoidf_dev(a1);
        v.z = sigmoidf_dev(a2); v.w = sigmoidf_dev(a3);
    }
    *(float4*)&out[(size_t)m * OO + o] = v;
}

extern "C" void kernel_launch(void* const* d_in, const int* in_sizes, int n_in,
                              void* d_out, int out_size) {
    const float* x      = (const float*)d_in[0];
    const float* W1     = (const float*)d_in[1];
    const float* b1     = (const float*)d_in[2];
    const float* tau_m1 = (const float*)d_in[3];
    const float* tau_n1 = (const float*)d_in[4];
    const float* W2     = (const float*)d_in[5];
    const float* b2     = (const float*)d_in[6];
    const float* tau_m2 = (const float*)d_in[7];
    const float* tau_n2 = (const float*)d_in[8];
    const float* Wo     = (const float*)d_in[9];
    const float* bo     = (const float*)d_in[10];
    float* out = (float*)d_out;

    static int smem_set = 0;
    if (!smem_set) {
        cudaFuncSetAttribute(fused_gemm_scan1,
                             cudaFuncAttributeMaxDynamicSharedMemorySize,
                             SMEM_BYTES);
        smem_set = 1;
    }

    // 0) prep (3 launches; keeps fused at launch #4 for ncu)
    prep_zero<<<(MM + 255) / 256, 256>>>();
    prep_w1<<<(H1 * II / 4 + 255) / 256, 256>>>(W1, bo);
    prep_x<<<(MM * II / 16 + 255) / 256, 256>>>(x);

    // 1+2) warp-specialized fused layer-1 projection + LIF scan
    dim3 grid(H1 / 128, BB);   // (4 h-tiles, 64 batches) = 256 CTAs
    fused_gemm_scan1<<<grid, 384, SMEM_BYTES>>>(b1, tau_m1, tau_n1);

    // 3) layer-2 LIF scan (closed-form chunk jumps, certified spike-free)
    scan2_kernel<<<(BB * H2) / 128, 128>>>(b2, tau_m2, tau_n2, W2);

    // 4) output projection
    out_proj<<<MM / 8, 256>>>(bo, Wo, out);
}